// round 2
// baseline (speedup 1.0000x reference)
#include <cuda_runtime.h>
#include <cuda_bf16.h>

// AlphaRotatedIoULoss: loss = mean(1 - max(IoU_rot, 1e-6)^3) over N rotated-box pairs.
// Strategy: convex-quad intersection via Sutherland-Hodgman clipping (exact same
// area as the reference's hull-sort formulation, far fewer ops).

#define NPAIRS_EXPECTED 1000000

static __device__ double g_acc;

__global__ void arl_zero_kernel() {
    g_acc = 0.0;
}

__device__ __forceinline__ float cross2(float ax, float ay, float bx, float by) {
    return ax * by - ay * bx;
}

__global__ __launch_bounds__(256) void arl_loss_kernel(
    const float* __restrict__ pred,
    const float* __restrict__ tgt,
    int n)
{
    int i = blockIdx.x * blockDim.x + threadIdx.x;
    float loss = 0.0f;

    if (i < n) {
        const float* p = pred + 5 * i;
        const float* t = tgt + 5 * i;
        float x1 = p[0], y1 = p[1], w1 = p[2], h1 = p[3], a1 = p[4];
        float x2 = t[0], y2 = t[1], w2 = t[2], h2 = t[3], a2 = t[4];

        float s1, c1, s2, c2;
        __sincosf(a1, &s1, &c1);
        __sincosf(a2, &s2, &c2);

        float hw1 = 0.5f * w1, hh1 = 0.5f * h1;
        float hw2 = 0.5f * w2, hh2 = 0.5f * h2;

        // Corners CCW: (-hw,-hh), (hw,-hh), (hw,hh), (-hw,hh) rotated by a, translated.
        // X = x + dx*c - dy*s ; Y = y + dx*s + dy*c
        float wcx1 = hw1 * c1, wsx1 = hw1 * s1, hcx1 = hh1 * c1, hsx1 = hh1 * s1;
        float px[8], py[8];
        px[0] = x1 - wcx1 + hsx1;  py[0] = y1 - wsx1 - hcx1;
        px[1] = x1 + wcx1 + hsx1;  py[1] = y1 + wsx1 - hcx1;
        px[2] = x1 + wcx1 - hsx1;  py[2] = y1 + wsx1 + hcx1;
        px[3] = x1 - wcx1 - hsx1;  py[3] = y1 - wsx1 + hcx1;

        float wcx2 = hw2 * c2, wsx2 = hw2 * s2, hcx2 = hh2 * c2, hsx2 = hh2 * s2;
        float cx[4], cy[4];
        cx[0] = x2 - wcx2 + hsx2;  cy[0] = y2 - wsx2 - hcx2;
        cx[1] = x2 + wcx2 + hsx2;  cy[1] = y2 + wsx2 - hcx2;
        cx[2] = x2 + wcx2 - hsx2;  cy[2] = y2 + wsx2 + hcx2;
        cx[3] = x2 - wcx2 - hsx2;  cy[3] = y2 - wsx2 + hcx2;

        // Sutherland-Hodgman: clip subject poly (box1) by the 4 CCW edges of box2.
        float qx[8], qy[8];
        int nv = 4;

        #pragma unroll
        for (int e = 0; e < 4; e++) {
            float ax = cx[e],            ay = cy[e];
            float bx = cx[(e + 1) & 3],  by = cy[(e + 1) & 3];
            float ex = bx - ax, ey = by - ay;

            float* inx  = (e & 1) ? qx : px;
            float* iny  = (e & 1) ? qy : py;
            float* outx = (e & 1) ? px : qx;
            float* outy = (e & 1) ? py : qy;

            int m = 0;
            if (nv > 0) {
                float sx = inx[nv - 1], sy = iny[nv - 1];
                float ds = ex * (sy - ay) - ey * (sx - ax);
                for (int j = 0; j < nv; j++) {
                    float vx = inx[j], vy = iny[j];
                    float dv = ex * (vy - ay) - ey * (vx - ax);
                    if (dv >= 0.0f) {
                        if (ds < 0.0f) {
                            float tt = ds / (ds - dv);
                            outx[m] = sx + tt * (vx - sx);
                            outy[m] = sy + tt * (vy - sy);
                            m++;
                        }
                        outx[m] = vx; outy[m] = vy; m++;
                    } else if (ds >= 0.0f) {
                        float tt = ds / (ds - dv);
                        outx[m] = sx + tt * (vx - sx);
                        outy[m] = sy + tt * (vy - sy);
                        m++;
                    }
                    sx = vx; sy = vy; ds = dv;
                }
            }
            nv = m;
        }

        // After 4 clips (even count), result lives in px/py.
        float inter = 0.0f;
        if (nv >= 3) {
            float acc = 0.0f;
            float lx = px[nv - 1], ly = py[nv - 1];
            for (int j = 0; j < nv; j++) {
                float vx = px[j], vy = py[j];
                acc += lx * vy - vx * ly;
                lx = vx; ly = vy;
            }
            inter = 0.5f * fabsf(acc);
        }

        float area1 = w1 * h1;
        float area2 = w2 * h2;
        float iou = inter / (area1 + area2 - inter);
        iou = fmaxf(iou, 1e-6f);
        loss = 1.0f - iou * iou * iou;
    }

    // Block reduction: warp shuffle, then smem across 8 warps, one double atomic.
    #pragma unroll
    for (int off = 16; off > 0; off >>= 1)
        loss += __shfl_down_sync(0xffffffffu, loss, off);

    __shared__ float wsum[8];
    int lane = threadIdx.x & 31;
    int wid  = threadIdx.x >> 5;
    if (lane == 0) wsum[wid] = loss;
    __syncthreads();
    if (wid == 0) {
        float v = (lane < 8) ? wsum[lane] : 0.0f;
        #pragma unroll
        for (int off = 4; off > 0; off >>= 1)
            v += __shfl_down_sync(0xffu, v, off);
        if (lane == 0)
            atomicAdd(&g_acc, (double)v);
    }
}

__global__ void arl_finalize_kernel(float* __restrict__ out, float inv_n) {
    out[0] = (float)(g_acc * (double)inv_n);
}

extern "C" void kernel_launch(void* const* d_in, const int* in_sizes, int n_in,
                              void* d_out, int out_size)
{
    const float* pred = (const float*)d_in[0];
    const float* tgt  = (const float*)d_in[1];
    float* out = (float*)d_out;
    int n = in_sizes[0] / 5;

    arl_zero_kernel<<<1, 1>>>();
    int threads = 256;
    int blocks = (n + threads - 1) / threads;
    arl_loss_kernel<<<blocks, threads>>>(pred, tgt, n);
    arl_finalize_kernel<<<1, 1>>>(out, 1.0f / (float)n);
}

// round 5
// speedup vs baseline: 3.0975x; 3.0975x over previous
#include <cuda_runtime.h>
#include <cuda_bf16.h>

// AlphaRotatedIoULoss: loss = mean(1 - max(IoU_rot, 1e-6)^3) over N rotated-box pairs.
// Round 3: branchless register-resident convex clip.
//   - Transform box1 into box2's local frame (box2 becomes axis-aligned slab pair).
//   - Slab clip emits exactly 2 points per edge (inside sub-segment, or both
//     endpoints projected onto the boundary line when fully outside). Collinear
//     points on the clip line contribute identically under shoelace, so no
//     compaction is needed and the whole pipeline is static-indexed -> registers.
//   - 4 corners -> x-slab (8 pts) -> y-slab with fused shoelace accumulation.

static __device__ double g_acc;

__global__ void arl_zero_kernel() {
    g_acc = 0.0;
}

// Clip edge (sx,sy)->(vx,vy) against slab  -W <= x <= W.
// Emits two points (ax,ay), (bx,by): the inside sub-segment if it exists,
// otherwise both endpoints projected onto the (single, shared) boundary line.
__device__ __forceinline__ void slab_edge(
    float sx, float sy, float vx, float vy, float W,
    float& ax, float& ay, float& bx, float& by)
{
    float dx = vx - sx;
    float dy = vy - sy;
    float adx = fabsf(dx);
    float dxs = (adx > 1e-12f) ? dx : copysignf(1e-12f, dx);
    float inv = __fdividef(1.0f, dxs);
    float tA = (-W - sx) * inv;
    float tB = ( W - sx) * inv;
    float tmin = fminf(tA, tB);
    float tmax = fmaxf(tA, tB);
    float t0 = fmaxf(tmin, 0.0f);
    float t1 = fminf(tmax, 1.0f);
    bool empty = (t0 > t1);   // edge entirely outside the slab (one side)
    float iax = fmaf(t0, dx, sx), iay = fmaf(t0, dy, sy);
    float ibx = fmaf(t1, dx, sx), iby = fmaf(t1, dy, sy);
    float pax = fminf(fmaxf(sx, -W), W);   // projection onto boundary line
    float pbx = fminf(fmaxf(vx, -W), W);
    ax = empty ? pax : iax;
    ay = empty ? sy  : iay;
    bx = empty ? pbx : ibx;
    by = empty ? vy  : iby;
}

__global__ __launch_bounds__(256) void arl_loss_kernel(
    const float* __restrict__ pred,
    const float* __restrict__ tgt,
    int n)
{
    int i = blockIdx.x * blockDim.x + threadIdx.x;
    float loss = 0.0f;

    if (i < n) {
        const float* p = pred + 5 * i;
        const float* t = tgt + 5 * i;
        float x1 = __ldg(p + 0), y1 = __ldg(p + 1), w1 = __ldg(p + 2),
              h1 = __ldg(p + 3), a1 = __ldg(p + 4);
        float x2 = __ldg(t + 0), y2 = __ldg(t + 1), w2 = __ldg(t + 2),
              h2 = __ldg(t + 3), a2 = __ldg(t + 4);

        float s2f, c2f;
        __sincosf(a2, &s2f, &c2f);
        float s1f, c1f;
        __sincosf(a1, &s1f, &c1f);

        // Box1 center in box2's local frame.
        float rx = x1 - x2, ry = y1 - y2;
        float lx =  rx * c2f + ry * s2f;
        float ly = -rx * s2f + ry * c2f;

        // Relative rotation: c = cos(a1-a2), s = sin(a1-a2).
        float c = c1f * c2f + s1f * s2f;
        float s = s1f * c2f - c1f * s2f;

        float hw1 = 0.5f * w1, hh1 = 0.5f * h1;
        float W = 0.5f * w2,  H = 0.5f * h2;

        float wx = hw1 * c, wy = hw1 * s;
        float hx = -hh1 * s, hy = hh1 * c;

        // Box1 corners (CCW) in box2 frame.
        float kx[4], ky[4];
        kx[0] = lx - wx - hx;  ky[0] = ly - wy - hy;
        kx[1] = lx + wx - hx;  ky[1] = ly + wy - hy;
        kx[2] = lx + wx + hx;  ky[2] = ly + wy + hy;
        kx[3] = lx - wx + hx;  ky[3] = ly - wy + hy;

        // Stage 1: clip against |x| <= W. 4 edges -> 8 points (static indexing).
        float Px[8], Py[8];
        #pragma unroll
        for (int e = 0; e < 4; e++) {
            int e1 = (e + 1) & 3;
            slab_edge(kx[e], ky[e], kx[e1], ky[e1], W,
                      Px[2 * e], Py[2 * e], Px[2 * e + 1], Py[2 * e + 1]);
        }

        // Stage 2: clip against |y| <= H, fusing the shoelace accumulation.
        float acc = 0.0f;
        float a0x = 0.0f, a0y = 0.0f;     // first emitted point (for wraparound)
        float pbx = 0.0f, pby = 0.0f;     // previous emitted b
        #pragma unroll
        for (int e = 0; e < 8; e++) {
            int e1 = (e + 1) & 7;
            float ax, ay, bx, by;
            // Swap coordinate roles: clip y against [-H, H].
            slab_edge(Py[e], Px[e], Py[e1], Px[e1], H, ay, ax, by, bx);
            if (e == 0) { a0x = ax; a0y = ay; }
            else        { acc += pbx * ay - ax * pby; }
            acc += ax * by - bx * ay;
            pbx = bx; pby = by;
        }
        acc += pbx * a0y - a0x * pby;

        float inter = 0.5f * fabsf(acc);
        float area1 = w1 * h1;
        float area2 = w2 * h2;
        float iou = __fdividef(inter, area1 + area2 - inter);
        iou = fmaxf(iou, 1e-6f);
        loss = 1.0f - iou * iou * iou;
    }

    // Block reduction: warp shuffle, then smem across 8 warps, one double atomic.
    #pragma unroll
    for (int off = 16; off > 0; off >>= 1)
        loss += __shfl_down_sync(0xffffffffu, loss, off);

    __shared__ float wsum[8];
    int lane = threadIdx.x & 31;
    int wid  = threadIdx.x >> 5;
    if (lane == 0) wsum[wid] = loss;
    __syncthreads();
    if (wid == 0) {
        float v = (lane < 8) ? wsum[lane] : 0.0f;
        #pragma unroll
        for (int off = 4; off > 0; off >>= 1)
            v += __shfl_down_sync(0xffu, v, off);
        if (lane == 0)
            atomicAdd(&g_acc, (double)v);
    }
}

__global__ void arl_finalize_kernel(float* __restrict__ out, float inv_n) {
    out[0] = (float)(g_acc * (double)inv_n);
}

extern "C" void kernel_launch(void* const* d_in, const int* in_sizes, int n_in,
                              void* d_out, int out_size)
{
    const float* pred = (const float*)d_in[0];
    const float* tgt  = (const float*)d_in[1];
    float* out = (float*)d_out;
    int n = in_sizes[0] / 5;

    arl_zero_kernel<<<1, 1>>>();
    int threads = 256;
    int blocks = (n + threads - 1) / threads;
    arl_loss_kernel<<<blocks, threads>>>(pred, tgt, n);
    arl_finalize_kernel<<<1, 1>>>(out, 1.0f / (float)n);
}